// round 16
// baseline (speedup 1.0000x reference)
#include <cuda_runtime.h>

// Fixed problem shape
#define HH   50
#define GG   200
#define TT   2048
#define BB   8192
#define BPB  64          // batches per block
#define NW   8           // warps: each owns 8 batches (4 f32x2 pairs)
#define NTHR 256
#define XROW 66
#define WROW 60          // wsh row stride (floats); 15 16B-units, odd -> conflict-free LDS.128
#define HSTR 52          // hw stride per pair (ull); j=50,51 stay zero (quad padding)
#define ZSTR 200         // zw stride per pair (ull)
#define TSTR 53          // wtail row stride (ull); conflict-free for 8-row access

typedef unsigned long long ull;

// ---- packed f32x2 helpers (PTX-only) ----
__device__ __forceinline__ ull pack2(float lo, float hi) {
    ull r; asm("mov.b64 %0, {%1, %2};" : "=l"(r) : "f"(lo), "f"(hi)); return r;
}
__device__ __forceinline__ void unpack2(ull v, float &lo, float &hi) {
    asm("mov.b64 {%0, %1}, %2;" : "=f"(lo), "=f"(hi) : "l"(v));
}
__device__ __forceinline__ ull ffma2(ull a, ull b, ull c) {
    ull d; asm("fma.rn.f32x2 %0, %1, %2, %3;" : "=l"(d) : "l"(a), "l"(b), "l"(c)); return d;
}

// ---- MUFU.TANH activations (validated: rel_err ~2e-6) ----
__device__ __forceinline__ float tanha(float x) {
    float r; asm("tanh.approx.f32 %0, %1;" : "=f"(r) : "f"(x)); return r;
}
__device__ __forceinline__ float sigm(float x) {       // 0.5*tanh(x/2)+0.5
    return fmaf(0.5f, tanha(0.5f * x), 0.5f);
}

// ---- shared layout (bytes) ----
// wsh  : float[200][60]    48000 @ 0       W_hh rows, j-padded to 60 (50..59 zero)
// wbsh : float2[200]        1600 @ 48000   (W_ih[g], b_ih+b_hh)
// wlin : float[52]           208 @ 49600
// xt   : float[64][66]     16896 @ 49824
// hw   : ull[8][4][52]     13312 @ 66720   per-warp h, [pair][j] packed (b0,b1); j 50,51 = 0
// zw   : ull[8][4][200]    51200 @ 80032   per-warp z, [pair][gate row] packed
// wtail: ull[8][53]         3392 @ 131232  dup'd W_hh rows 192..199
#define OFF_W    0
#define OFF_WB   48000
#define OFF_WLIN 49600
#define OFF_X    49824
#define OFF_HW   66720
#define OFF_ZW   80032
#define OFF_WT   131232
#define SMEM_BYTES 134624

// load one quad's weights (rows l+32s, cols j0..j0+3) into buffer
__device__ __forceinline__ void qload(int j0, int l,
                                      const float* __restrict__ wsh,
                                      float4 w4[6])
{
#pragma unroll
    for (int s = 0; s < 6; ++s)
        w4[s] = *(const float4*)&wsh[(l + 32 * s) * WROW + j0];
}

// consume one quad: FFMA2s for 4 j, 6 s-rows, 4 pairs (h loaded here, broadcast)
__device__ __forceinline__ void qmath(int j0,
                                      const float4 w4[6],
                                      const ull* __restrict__ hw,
                                      ull acc[4][6])
{
    ull h4[4][4];
#pragma unroll
    for (int p = 0; p < 4; ++p) {
        ulonglong2 a = *(const ulonglong2*)&hw[p * HSTR + j0];
        ulonglong2 b = *(const ulonglong2*)&hw[p * HSTR + j0 + 2];
        h4[p][0] = a.x; h4[p][1] = a.y; h4[p][2] = b.x; h4[p][3] = b.y;
    }
#pragma unroll
    for (int jj = 0; jj < 4; ++jj) {
#pragma unroll
        for (int s = 0; s < 6; ++s) {
            const float wv = (jj == 0) ? w4[s].x : (jj == 1) ? w4[s].y
                           : (jj == 2) ? w4[s].z : w4[s].w;
            const ull w2 = pack2(wv, wv);
#pragma unroll
            for (int p = 0; p < 4; ++p)
                acc[p][s] = ffma2(w2, h4[p][jj], acc[p][s]);
        }
    }
}

// one activation task: element (pair p, hidden j), both batches
__device__ __forceinline__ void act_one(ull* __restrict__ zw, ull* __restrict__ hw,
                                        int p, int j, float* cs)
{
    float zi0, zi1, zf0, zf1, zg0, zg1, zo0, zo1;
    unpack2(zw[p * ZSTR +       j], zi0, zi1);
    unpack2(zw[p * ZSTR +  50 + j], zf0, zf1);
    unpack2(zw[p * ZSTR + 100 + j], zg0, zg1);
    unpack2(zw[p * ZSTR + 150 + j], zo0, zo1);
    float h0, h1;
    {
        const float iv = sigm(zi0), fv = sigm(zf0);
        const float gv = tanha(zg0), ov = sigm(zo0);
        const float c  = fmaf(fv, cs[0], iv * gv);
        cs[0] = c;
        h0 = ov * tanha(c);
    }
    {
        const float iv = sigm(zi1), fv = sigm(zf1);
        const float gv = tanha(zg1), ov = sigm(zo1);
        const float c  = fmaf(fv, cs[1], iv * gv);
        cs[1] = c;
        h1 = ov * tanha(c);
    }
    hw[p * HSTR + j] = pack2(h0, h1);
}

__global__ __launch_bounds__(NTHR, 1)
void lstm_persist_kernel(const float* __restrict__ x,
                         const float* __restrict__ W_ih,
                         const float* __restrict__ W_hh,
                         const float* __restrict__ b_ih,
                         const float* __restrict__ b_hh,
                         const float* __restrict__ W_lin,
                         const float* __restrict__ b_lin,
                         float* __restrict__ out)
{
    extern __shared__ char smem[];
    float*  wsh  = (float*)(smem + OFF_W);
    float2* wbsh = (float2*)(smem + OFF_WB);
    float*  wlin = (float*)(smem + OFF_WLIN);
    float*  xt   = (float*)(smem + OFF_X);
    ull*    wtail= (ull*)(smem + OFF_WT);

    const int tid = threadIdx.x;
    const int w   = tid >> 5;
    const int l   = tid & 31;

    ull* __restrict__ hw = (ull*)(smem + OFF_HW) + w * (4 * HSTR);
    ull* __restrict__ zw = (ull*)(smem + OFF_ZW) + w * (4 * ZSTR);

    // ---- init shared ----
    for (int i = tid; i < GG * WROW; i += NTHR) {
        int g = i / WROW, j = i - g * WROW;
        wsh[i] = (j < HH) ? W_hh[g * HH + j] : 0.0f;
    }
    for (int g = tid; g < GG; g += NTHR)
        wbsh[g] = make_float2(W_ih[g], b_ih[g] + b_hh[g]);
    for (int i = tid; i < 52; i += NTHR)
        wlin[i] = (i < HH) ? W_lin[i] : 0.0f;
    for (int i = tid; i < 8 * TSTR; i += NTHR) {
        int r = i / TSTR, j = i - r * TSTR;
        float v = (j < HH) ? W_hh[(192 + r) * HH + j] : 0.0f;
        wtail[i] = pack2(v, v);
    }
    for (int i = tid; i < NW * 4 * HSTR; i += NTHR)
        ((ull*)(smem + OFF_HW))[i] = 0ull;
    for (int i = tid; i < NW * 4 * ZSTR; i += NTHR)   // zero z -> act(-1) is a no-op
        ((ull*)(smem + OFF_ZW))[i] = 0ull;

    const int bbase = blockIdx.x * BPB;
    const float* __restrict__ xg = x + (size_t)bbase * TT;

    // precomputed activation task maps (t-invariant)
    int p1[3], j1[3], p2[3], j2[3];
#pragma unroll
    for (int k = 0; k < 3; ++k) {
        const int a = l + 32 * k;
        p1[k] = a / 24;  j1[k] = a - 24 * p1[k];          // j < 24 part
        p2[k] = a / 26;  j2[k] = 24 + (a - 26 * p2[k]);   // j >= 24 part
    }
    float c1[3][2], c2[4][2];
#pragma unroll
    for (int k = 0; k < 3; ++k) { c1[k][0] = c1[k][1] = 0.0f; }
#pragma unroll
    for (int k = 0; k < 4; ++k) { c2[k][0] = c2[k][1] = 0.0f; }

    __syncthreads();

    // ---- hoisted t-invariant registers ----
    float2 wb[6];
#pragma unroll
    for (int s = 0; s < 6; ++s) wb[s] = wbsh[l + 32 * s];
    const float2 wbr = wbsh[192 + (l & 7)];   // tail row bias
    const ull* __restrict__ wtr = &wtail[(l & 7) * TSTR];
    const int tp = l >> 3;                     // tail pair

    float4 wA[6], wB[6];                       // pipelined weight buffers
    qload(0, l, wsh, wA);

    for (int t = 0; t < TT; ++t) {
        if ((t & 63) == 0) {
            __syncthreads();
            for (int idx = tid; idx < 64 * 64; idx += NTHR) {
                int tl = idx & 63, bb = idx >> 6;
                xt[tl * XROW + bb] = xg[(size_t)bb * TT + t + tl];
            }
            __syncthreads();
        }

        // ---- act(t-1), part 1: j < 24 (96 tasks, 3 exact rounds) ----
#pragma unroll
        for (int k = 0; k < 3; ++k) act_one(zw, hw, p1[k], j1[k], c1[k]);
        __syncwarp();

        // ---- region B: acc init; act(t-1) p2 interleaved with quads(t) j<24 ----
        const int xrow = (t & 63) * XROW;
        float2 xv[4];
#pragma unroll
        for (int p = 0; p < 4; ++p)
            xv[p] = *(const float2*)&xt[xrow + w * 8 + 2 * p];

        ull acc[4][6];
#pragma unroll
        for (int s = 0; s < 6; ++s)
#pragma unroll
            for (int p = 0; p < 4; ++p)
                acc[p][s] = pack2(fmaf(wb[s].x, xv[p].x, wb[s].y),
                                  fmaf(wb[s].x, xv[p].y, wb[s].y));

        act_one(zw, hw, p2[0], j2[0], c2[0]);
        qload( 4, l, wsh, wB);  qmath( 0, wA, hw, acc);
        qload( 8, l, wsh, wA);  qmath( 4, wB, hw, acc);
        act_one(zw, hw, p2[1], j2[1], c2[1]);
        qload(12, l, wsh, wB);  qmath( 8, wA, hw, acc);
        qload(16, l, wsh, wA);  qmath(12, wB, hw, acc);
        act_one(zw, hw, p2[2], j2[2], c2[2]);
        qload(20, l, wsh, wB);  qmath(16, wA, hw, acc);
        qload(24, l, wsh, wA);  qmath(20, wB, hw, acc);
        if (l < 8) act_one(zw, hw, 3, 42 + l, c2[3]);   // last 8 tasks of part 2
        __syncwarp();

        // ---- region C: quads j>=24, tail row, z stores ----
        qload(28, l, wsh, wB);  qmath(24, wA, hw, acc);
        qload(32, l, wsh, wA);  qmath(28, wB, hw, acc);
        qload(36, l, wsh, wB);  qmath(32, wA, hw, acc);
        qload(40, l, wsh, wA);  qmath(36, wB, hw, acc);
        qload(44, l, wsh, wB);  qmath(40, wA, hw, acc);
        qload(48, l, wsh, wA);  qmath(44, wB, hw, acc);
        qmath(48, wA, hw, acc);
        qload(0, l, wsh, wA);                            // refill w0 for next t

        {   // rows 192..199 (o-gate j=42..49): lane = (row, pair) combo
            ull ta = pack2(fmaf(wbr.x, xv[tp].x, wbr.y),
                           fmaf(wbr.x, xv[tp].y, wbr.y));
            const ull* __restrict__ hp = &hw[tp * HSTR];
#pragma unroll 10
            for (int j = 0; j < HH; ++j)
                ta = ffma2(wtr[j], hp[j], ta);
            zw[tp * ZSTR + 192 + (l & 7)] = ta;
        }

#pragma unroll
        for (int s = 0; s < 6; ++s)
#pragma unroll
            for (int p = 0; p < 4; ++p)
                zw[p * ZSTR + l + 32 * s] = acc[p][s];
        __syncwarp();
    }

    // ---- final act(TT-1) ----
#pragma unroll
    for (int k = 0; k < 3; ++k) act_one(zw, hw, p1[k], j1[k], c1[k]);
#pragma unroll
    for (int k = 0; k < 3; ++k) act_one(zw, hw, p2[k], j2[k], c2[k]);
    if (l < 8) act_one(zw, hw, 3, 42 + l, c2[3]);
    __syncwarp();

    // ---- final projection: lanes 0-7 -> this warp's 8 batches ----
    if (l < 8) {
        const int p  = l >> 1;
        const int hi = l & 1;
        float s = b_lin[0];
#pragma unroll
        for (int j = 0; j < HH; ++j) {
            float h0, h1;
            unpack2(hw[p * HSTR + j], h0, h1);
            s = fmaf(wlin[j], hi ? h1 : h0, s);
        }
        out[bbase + w * 8 + l] = s;
    }
}

extern "C" void kernel_launch(void* const* d_in, const int* in_sizes, int n_in,
                              void* d_out, int out_size)
{
    const float* x     = (const float*)d_in[0];
    const float* W_ih  = (const float*)d_in[1];
    const float* W_hh  = (const float*)d_in[2];
    const float* b_ih  = (const float*)d_in[3];
    const float* b_hh  = (const float*)d_in[4];
    const float* W_lin = (const float*)d_in[5];
    const float* b_lin = (const float*)d_in[6];
    float* out = (float*)d_out;

    cudaFuncSetAttribute(lstm_persist_kernel,
                         cudaFuncAttributeMaxDynamicSharedMemorySize, SMEM_BYTES);

    lstm_persist_kernel<<<BB / BPB, NTHR, SMEM_BYTES>>>(
        x, W_ih, W_hh, b_ih, b_hh, W_lin, b_lin, out);
}